// round 2
// baseline (speedup 1.0000x reference)
#include <cuda_runtime.h>

typedef unsigned long long ull;

#define NMAX 50000
#define EMAX 400000
#define ETOTMAX (EMAX + NMAX)
#define CAP 512

// ---------------- scratch ----------------
__device__ float g_h1[NMAX * 256];
__device__ float g_agg[NMAX * 256];
__device__ float g_asrc1[NMAX * 2];
__device__ float g_adst1[NMAX * 2];
__device__ float g_hm[NMAX * 64];
__device__ float g_hl[NMAX * 64];
__device__ float g_amu_s[NMAX], g_amu_d[NMAX];
__device__ float g_als_s[NMAX], g_als_d[NMAX];
__device__ int   g_cnt[NMAX];
__device__ int   g_ofs[NMAX + 1];
__device__ int   g_cur[NMAX];
__device__ int   g_src[ETOTMAX];

// ---------------- helpers ----------------
__device__ __forceinline__ ull pack2(float lo, float hi) {
    ull r; asm("mov.b64 %0, {%1, %2};" : "=l"(r) : "f"(lo), "f"(hi)); return r;
}
__device__ __forceinline__ void unpack2(ull v, float& lo, float& hi) {
    asm("mov.b64 {%0, %1}, %2;" : "=f"(lo), "=f"(hi) : "l"(v));
}
__device__ __forceinline__ void ffma2(ull& d, ull a, ull b) {
    asm("fma.rn.f32x2 %0, %1, %2, %0;" : "+l"(d) : "l"(a), "l"(b));
}
__device__ __forceinline__ float lrelu(float v) { return v > 0.f ? v : 0.2f * v; }
__device__ __forceinline__ float wredsum(float v) {
#pragma unroll
    for (int o = 16; o; o >>= 1) v += __shfl_xor_sync(0xFFFFFFFFu, v, o);
    return v;
}
__device__ __forceinline__ float wredmax(float v) {
#pragma unroll
    for (int o = 16; o; o >>= 1) v = fmaxf(v, __shfl_xor_sync(0xFFFFFFFFu, v, o));
    return v;
}

// ---------------- CSR build ----------------
__global__ void kzero(int n) {
    int i = blockIdx.x * blockDim.x + threadIdx.x;
    if (i < n) g_cnt[i] = 0;
}
__global__ void kcount(const int* __restrict__ ei, int E0, int Et) {
    int e = blockIdx.x * blockDim.x + threadIdx.x;
    if (e >= Et) return;
    int d = (e < E0) ? ei[E0 + e] : (e - E0);
    atomicAdd(&g_cnt[d], 1);
}
__global__ void kscan(int n) {
    __shared__ int wsum[32];
    int tid = threadIdx.x, lane = tid & 31, warp = tid >> 5;
    int carry = 0;
    for (int base = 0; base < n; base += 1024) {
        int i = base + tid;
        int v = (i < n) ? g_cnt[i] : 0;
        int x = v;
#pragma unroll
        for (int o = 1; o < 32; o <<= 1) {
            int t = __shfl_up_sync(0xFFFFFFFFu, x, o);
            if (lane >= o) x += t;
        }
        if (lane == 31) wsum[warp] = x;
        __syncthreads();
        if (warp == 0) {
            int s = wsum[lane];
#pragma unroll
            for (int o = 1; o < 32; o <<= 1) {
                int t = __shfl_up_sync(0xFFFFFFFFu, s, o);
                if (lane >= o) s += t;
            }
            wsum[lane] = s;
        }
        __syncthreads();
        int pre = warp ? wsum[warp - 1] : 0;
        int excl = carry + pre + x - v;
        if (i < n) { g_ofs[i] = excl; g_cur[i] = excl; }
        carry += wsum[31];
        __syncthreads();
    }
    if (tid == 0) g_ofs[n] = carry;
}
__global__ void kfill(const int* __restrict__ ei, int E0, int Et) {
    int e = blockIdx.x * blockDim.x + threadIdx.x;
    if (e >= Et) return;
    int s = (e < E0) ? ei[e] : (e - E0);
    int d = (e < E0) ? ei[E0 + e] : (e - E0);
    int pos = atomicAdd(&g_cur[d], 1);
    g_src[pos] = s;
}

// ---------------- GEMM1: h1 = x @ W1 (+ attention dots), FFMA2 k-pair packed ----
// 512 threads: 16 warps x 4 nodes (M-tile 64), lanes cover 256 cols (8 each).
__global__ __launch_bounds__(512, 1) void gemm1(
    const float* __restrict__ x, const float* __restrict__ W1,
    const float* __restrict__ attS, const float* __restrict__ attD, int n)
{
    __shared__ __align__(16) float xs[64 * 32];   // [node][kk]
    __shared__ __align__(16) float ws[32 * 256];  // [kk][c]
    const int tid = threadIdx.x, lane = tid & 31, wi = tid >> 5;
    const int n0 = blockIdx.x * 64;
    const int nn = min(64, n - n0);

    ull acc[4][8];
#pragma unroll
    for (int i = 0; i < 4; i++)
#pragma unroll
        for (int c = 0; c < 8; c++) acc[i][c] = 0ull;

    const ull* xs64 = (const ull*)xs;

    for (int k0 = 0; k0 < 128; k0 += 32) {
        __syncthreads();
        for (int idx = tid; idx < 64 * 32; idx += 512) {
            int node = idx >> 5, kk = idx & 31;
            xs[idx] = (node < nn) ? x[(long)(n0 + node) * 128 + k0 + kk] : 0.f;
        }
        for (int idx = tid; idx < 32 * 256; idx += 512) {
            int kk = idx >> 8, c = idx & 255;
            ws[idx] = W1[(long)(k0 + kk) * 256 + c];
        }
        __syncthreads();
#pragma unroll 4
        for (int kk2 = 0; kk2 < 16; kk2++) {
            ull xv[4], wv[8];
#pragma unroll
            for (int i = 0; i < 4; i++) xv[i] = xs64[(wi * 4 + i) * 16 + kk2];
#pragma unroll
            for (int cc = 0; cc < 8; cc++) {
                int c = lane + 32 * cc;
                wv[cc] = pack2(ws[(2 * kk2) * 256 + c], ws[(2 * kk2 + 1) * 256 + c]);
            }
#pragma unroll
            for (int i = 0; i < 4; i++)
#pragma unroll
                for (int cc = 0; cc < 8; cc++) ffma2(acc[i][cc], xv[i], wv[cc]);
        }
    }

    // epilogue: store h1, reduce attention dots per node & head
#pragma unroll
    for (int i = 0; i < 4; i++) {
        int node = wi * 4 + i;
        float ps0 = 0.f, pd0 = 0.f, ps1 = 0.f, pd1 = 0.f;
#pragma unroll
        for (int cc = 0; cc < 8; cc++) {
            float lo, hi; unpack2(acc[i][cc], lo, hi);
            float v = lo + hi;
            int c = lane + 32 * cc;
            if (node < nn) g_h1[(long)(n0 + node) * 256 + c] = v;
            float as = attS[c], ad = attD[c];
            if (cc < 4) { ps0 += v * as; pd0 += v * ad; }
            else        { ps1 += v * as; pd1 += v * ad; }
        }
        ps0 = wredsum(ps0); pd0 = wredsum(pd0);
        ps1 = wredsum(ps1); pd1 = wredsum(pd1);
        if (lane == 0 && node < nn) {
            int gn = n0 + node;
            g_asrc1[gn * 2 + 0] = ps0; g_asrc1[gn * 2 + 1] = ps1;
            g_adst1[gn * 2 + 0] = pd0; g_adst1[gn * 2 + 1] = pd1;
        }
    }
}

// ---------------- gather1: per-dst softmax + aggregate + bias + ELU ----------------
__global__ __launch_bounds__(256) void gather1(const float* __restrict__ b1) {
    __shared__ int   ssrc[CAP];
    __shared__ float ev0[CAP], ev1[CAP];
    __shared__ float par[4];
    const int d = blockIdx.x;
    const int tid = threadIdx.x;
    const int beg = g_ofs[d];
    const int deg = g_ofs[d + 1] - beg;

    if (tid < 32) {
        float ad0 = g_adst1[d * 2 + 0], ad1 = g_adst1[d * 2 + 1];
        float m0 = -1e30f, m1 = -1e30f;
        for (int i = tid; i < deg; i += 32) {
            int s = g_src[beg + i];
            float2 a = ((const float2*)g_asrc1)[s];
            float v0 = lrelu(a.x + ad0);
            float v1 = lrelu(a.y + ad1);
            if (i < CAP) { ssrc[i] = s; ev0[i] = v0; ev1[i] = v1; }
            m0 = fmaxf(m0, v0); m1 = fmaxf(m1, v1);
        }
        m0 = wredmax(m0); m1 = wredmax(m1);
        float s0 = 0.f, s1 = 0.f;
        for (int i = tid; i < deg; i += 32) {
            float v0, v1;
            if (i < CAP) { v0 = ev0[i]; v1 = ev1[i]; }
            else {
                int s = g_src[beg + i];
                float2 a = ((const float2*)g_asrc1)[s];
                v0 = lrelu(a.x + ad0); v1 = lrelu(a.y + ad1);
            }
            float w0 = __expf(v0 - m0), w1 = __expf(v1 - m1);
            if (i < CAP) { ev0[i] = w0; ev1[i] = w1; }
            s0 += w0; s1 += w1;
        }
        s0 = wredsum(s0); s1 = wredsum(s1);
        if (tid == 0) {
            par[0] = m0; par[1] = m1;
            par[2] = 1.f / (s0 + 1e-16f); par[3] = 1.f / (s1 + 1e-16f);
        }
    }
    __syncthreads();

    const int h = tid >> 7;
    const float m = par[h], inv = par[2 + h];
    const float adh = g_adst1[d * 2 + h];
    float acc = 0.f;
    for (int i = 0; i < deg; i++) {
        int s; float w;
        if (i < CAP) { s = ssrc[i]; w = h ? ev1[i] : ev0[i]; }
        else {
            s = g_src[beg + i];
            float v = lrelu(g_asrc1[s * 2 + h] + adh);
            w = __expf(v - m);
        }
        acc += (w * inv) * g_h1[(long)s * 256 + tid];
    }
    float v = acc + b1[tid];
    g_agg[(long)d * 256 + tid] = v > 0.f ? v : expm1f(v);
}

// ---------------- GEMM2: [hm|hl] = agg @ [Wm|Wl] (+ attention dots) ----------------
// 256 threads: 8 warps x 8 nodes (M-tile 64), lanes cover 128 cols (4 each).
__global__ __launch_bounds__(256, 2) void gemm2(
    const float* __restrict__ Wm, const float* __restrict__ Wl,
    const float* __restrict__ aSm, const float* __restrict__ aDm,
    const float* __restrict__ aSl, const float* __restrict__ aDl, int n)
{
    __shared__ __align__(16) float xs[64 * 32];   // [node][kk]
    __shared__ __align__(16) float ws[32 * 128];  // [kk][c]
    const int tid = threadIdx.x, lane = tid & 31, wi = tid >> 5;
    const int n0 = blockIdx.x * 64;
    const int nn = min(64, n - n0);

    ull acc[8][4];
#pragma unroll
    for (int i = 0; i < 8; i++)
#pragma unroll
        for (int c = 0; c < 4; c++) acc[i][c] = 0ull;

    const ull* xs64 = (const ull*)xs;

    for (int k0 = 0; k0 < 256; k0 += 32) {
        __syncthreads();
        for (int idx = tid; idx < 64 * 32; idx += 256) {
            int node = idx >> 5, kk = idx & 31;
            xs[idx] = (node < nn) ? g_agg[(long)(n0 + node) * 256 + k0 + kk] : 0.f;
        }
        for (int idx = tid; idx < 32 * 128; idx += 256) {
            int kk = idx >> 7, c = idx & 127;
            ws[idx] = (c < 64) ? Wm[(long)(k0 + kk) * 64 + c]
                               : Wl[(long)(k0 + kk) * 64 + (c - 64)];
        }
        __syncthreads();
#pragma unroll 4
        for (int kk2 = 0; kk2 < 16; kk2++) {
            ull xv[8], wv[4];
#pragma unroll
            for (int i = 0; i < 8; i++) xv[i] = xs64[(wi * 8 + i) * 16 + kk2];
#pragma unroll
            for (int cc = 0; cc < 4; cc++) {
                int c = lane + 32 * cc;
                wv[cc] = pack2(ws[(2 * kk2) * 128 + c], ws[(2 * kk2 + 1) * 128 + c]);
            }
#pragma unroll
            for (int i = 0; i < 8; i++)
#pragma unroll
                for (int cc = 0; cc < 4; cc++) ffma2(acc[i][cc], xv[i], wv[cc]);
        }
    }

#pragma unroll
    for (int i = 0; i < 8; i++) {
        int node = wi * 8 + i;
        float pms = 0.f, pmd = 0.f, pls = 0.f, pld = 0.f;
#pragma unroll
        for (int cc = 0; cc < 4; cc++) {
            float lo, hi; unpack2(acc[i][cc], lo, hi);
            float v = lo + hi;
            int c = lane + 32 * cc;
            if (cc < 2) {
                if (node < nn) g_hm[(long)(n0 + node) * 64 + c] = v;
                pms += v * aSm[c]; pmd += v * aDm[c];
            } else {
                int cl = c - 64;
                if (node < nn) g_hl[(long)(n0 + node) * 64 + cl] = v;
                pls += v * aSl[cl]; pld += v * aDl[cl];
            }
        }
        pms = wredsum(pms); pmd = wredsum(pmd);
        pls = wredsum(pls); pld = wredsum(pld);
        if (lane == 0 && node < nn) {
            int gn = n0 + node;
            g_amu_s[gn] = pms; g_amu_d[gn] = pmd;
            g_als_s[gn] = pls; g_als_d[gn] = pld;
        }
    }
}

// ---------------- gather2: per-dst softmax + aggregate for mu & logstd ----------------
__global__ __launch_bounds__(128) void gather2(
    float* __restrict__ out, const float* __restrict__ bm,
    const float* __restrict__ bl, int n)
{
    __shared__ int   ssrc[CAP];
    __shared__ float evm[CAP], evl[CAP];
    __shared__ float par[4];
    const int d = blockIdx.x;
    const int tid = threadIdx.x;
    const int beg = g_ofs[d];
    const int deg = g_ofs[d + 1] - beg;
    const int warp = tid >> 5;

    if (warp == 0) {  // mu logits
        float ad = g_amu_d[d];
        float m = -1e30f;
        for (int i = tid; i < deg; i += 32) {
            int s = g_src[beg + i];
            float v = lrelu(g_amu_s[s] + ad);
            if (i < CAP) { ssrc[i] = s; evm[i] = v; }
            m = fmaxf(m, v);
        }
        m = wredmax(m);
        float sum = 0.f;
        for (int i = tid; i < deg; i += 32) {
            float v = (i < CAP) ? evm[i] : lrelu(g_amu_s[g_src[beg + i]] + ad);
            float w = __expf(v - m);
            if (i < CAP) evm[i] = w;
            sum += w;
        }
        sum = wredsum(sum);
        if (tid == 0) { par[0] = m; par[1] = 1.f / (sum + 1e-16f); }
    } else if (warp == 1) {  // logstd logits
        int lane = tid & 31;
        float ad = g_als_d[d];
        float m = -1e30f;
        for (int i = lane; i < deg; i += 32) {
            int s = g_src[beg + i];
            float v = lrelu(g_als_s[s] + ad);
            if (i < CAP) evl[i] = v;
            m = fmaxf(m, v);
        }
        m = wredmax(m);
        float sum = 0.f;
        for (int i = lane; i < deg; i += 32) {
            float v = (i < CAP) ? evl[i] : lrelu(g_als_s[g_src[beg + i]] + ad);
            float w = __expf(v - m);
            if (i < CAP) evl[i] = w;
            sum += w;
        }
        sum = wredsum(sum);
        if (lane == 0) { par[2] = m; par[3] = 1.f / (sum + 1e-16f); }
    }
    __syncthreads();

    const int grp = tid >> 6;          // 0 = mu, 1 = ls
    const int c = tid & 63;
    const float m = par[grp * 2], inv = par[grp * 2 + 1];
    const float* hb = grp ? g_hl : g_hm;
    const float adh = grp ? g_als_d[d] : g_amu_d[d];
    const float* asc = grp ? g_als_s : g_amu_s;
    float acc = 0.f;
    for (int i = 0; i < deg; i++) {
        int s; float w;
        if (i < CAP) { s = ssrc[i]; w = grp ? evl[i] : evm[i]; }
        else {
            s = g_src[beg + i];
            float v = lrelu(asc[s] + adh);
            w = __expf(v - m);
        }
        acc += (w * inv) * hb[(long)s * 64 + c];
    }
    float bias = grp ? bl[c] : bm[c];
    long off = grp ? ((long)(n + d) * 64 + c) : ((long)d * 64 + c);
    out[off] = acc + bias;
}

// ---------------- launch ----------------
extern "C" void kernel_launch(void* const* d_in, const int* in_sizes, int n_in,
                              void* d_out, int out_size) {
    const float* x     = (const float*)d_in[0];
    const int*   ei    = (const int*)d_in[1];
    const float* W1    = (const float*)d_in[2];
    const float* attS1 = (const float*)d_in[3];
    const float* attD1 = (const float*)d_in[4];
    const float* b1    = (const float*)d_in[5];
    const float* Wm    = (const float*)d_in[6];
    const float* aSm   = (const float*)d_in[7];
    const float* aDm   = (const float*)d_in[8];
    const float* bm    = (const float*)d_in[9];
    const float* Wl    = (const float*)d_in[10];
    const float* aSl   = (const float*)d_in[11];
    const float* aDl   = (const float*)d_in[12];
    const float* bl    = (const float*)d_in[13];
    float* out = (float*)d_out;

    int n  = in_sizes[0] / 128;
    int E0 = in_sizes[1] / 2;
    int Et = E0 + n;
    int eb = (Et + 255) / 256;

    kzero<<<(n + 255) / 256, 256>>>(n);
    kcount<<<eb, 256>>>(ei, E0, Et);
    kscan<<<1, 1024>>>(n);
    kfill<<<eb, 256>>>(ei, E0, Et);

    gemm1<<<(n + 63) / 64, 512>>>(x, W1, attS1, attD1, n);
    gather1<<<n, 256>>>(b1);
    gemm2<<<(n + 63) / 64, 256>>>(Wm, Wl, aSm, aDm, aSl, aDl, n);
    gather2<<<n, 128>>>(out, bm, bl, n);
}

// round 3
// speedup vs baseline: 1.0701x; 1.0701x over previous
#include <cuda_runtime.h>

typedef unsigned long long ull;

#define NMAX 50000
#define EMAX 400000
#define ETOTMAX (EMAX + NMAX)
#define ENC_NEG 0x007FFFFFu   // encode(-inf)

// ---------------- scratch (device globals; no allocation allowed) ----------------
__device__ __align__(16) float g_h1[NMAX * 256];
__device__ __align__(16) float g_agg[NMAX * 256];
__device__ float    g_asrc1[NMAX * 2], g_adst1[NMAX * 2];
__device__ float    g_e1[ETOTMAX * 2];
__device__ unsigned g_max1[NMAX * 2];
__device__ float    g_sum1[NMAX * 2];

__device__ __align__(16) float g_hm[NMAX * 64];
__device__ __align__(16) float g_hl[NMAX * 64];
__device__ float    g_asrc_mu[NMAX], g_adst_mu[NMAX];
__device__ float    g_asrc_ls[NMAX], g_adst_ls[NMAX];
__device__ float    g_emu[ETOTMAX], g_els[ETOTMAX];
__device__ unsigned g_maxmu[NMAX], g_maxls[NMAX];
__device__ float    g_summu[NMAX], g_sumls[NMAX];

// ---------------- helpers ----------------
__device__ __forceinline__ unsigned fenc(float f) {
    int i = __float_as_int(f);
    return (i >= 0) ? ((unsigned)i | 0x80000000u) : ~(unsigned)i;
}
__device__ __forceinline__ float fdec(unsigned u) {
    int i = (u & 0x80000000u) ? (int)(u ^ 0x80000000u) : ~(int)u;
    return __int_as_float(i);
}
__device__ __forceinline__ float lrelu(float v) { return v > 0.f ? v : 0.2f * v; }

__device__ __forceinline__ ull pack2(float lo, float hi) {
    ull r; asm("mov.b64 %0, {%1, %2};" : "=l"(r) : "f"(lo), "f"(hi)); return r;
}
__device__ __forceinline__ void unpack2(ull v, float& lo, float& hi) {
    asm("mov.b64 {%0, %1}, %2;" : "=f"(lo), "=f"(hi) : "l"(v));
}
__device__ __forceinline__ void ffma2(ull& d, ull a, ull b) {
    asm("fma.rn.f32x2 %0, %1, %2, %0;" : "+l"(d) : "l"(a), "l"(b));
}

__device__ __forceinline__ void red4(float* p, float a, float b, float c, float d) {
    asm volatile("red.global.add.v4.f32 [%0], {%1,%2,%3,%4};"
                 :: "l"(__cvta_generic_to_global(p)), "f"(a), "f"(b), "f"(c), "f"(d)
                 : "memory");
}
__device__ __forceinline__ void red2(float* p, float a, float b) {
    asm volatile("red.global.add.v2.f32 [%0], {%1,%2};"
                 :: "l"(__cvta_generic_to_global(p)), "f"(a), "f"(b)
                 : "memory");
}

// ---------------- init ----------------
__global__ void kinit(int n, float* out) {
    long i = (long)blockIdx.x * blockDim.x + threadIdx.x;
    long na = (long)n * 256;
    if (i < na) g_agg[i] = 0.f;
    if (i < (long)2 * n * 64) out[i] = 0.f;
    if (i < (long)n * 2) { g_sum1[i] = 0.f; g_max1[i] = ENC_NEG; }
    if (i < n) {
        g_summu[i] = 0.f; g_sumls[i] = 0.f;
        g_maxmu[i] = ENC_NEG; g_maxls[i] = ENC_NEG;
    }
}

// ---------------- GEMM1: h1 = x @ W1 (+ attention dots), FFMA2 prepacked ----------
// 256 threads = 8 warps. M-tile = 32 nodes (lane = node). Warp wi owns cols
// [wi*32, wi*32+32). K tiled in chunks of 32 (16 k-pairs) packed as u64 in smem.
__global__ __launch_bounds__(256, 2) void gemm1(
    const float* __restrict__ x, const float* __restrict__ W1,
    const float* __restrict__ attS, const float* __restrict__ attD, int n)
{
    __shared__ __align__(16) ull xs[16 * 32];    // [k2][node]
    __shared__ __align__(16) ull ws[16 * 256];   // [k2][c]
    __shared__ float s_ps[8][32], s_pd[8][32];
    const int tid = threadIdx.x, lane = tid & 31, wi = tid >> 5;
    const int n0 = blockIdx.x * 32;
    const int nn = min(32, n - n0);
    const int cbase = wi * 32;
    const int node = lane;

    ull acc[32];
#pragma unroll
    for (int j = 0; j < 32; j++) acc[j] = 0ull;

    for (int k0 = 0; k0 < 128; k0 += 32) {
        __syncthreads();
        // pack x k-pairs: xs[k2][node]
#pragma unroll
        for (int i = 0; i < 2; i++) {
            int idx = tid + i * 256;            // 512 entries
            int nd = idx & 31, k2 = idx >> 5;
            ull v = 0ull;
            if (nd < nn)
                v = ((const ull*)(x + (long)(n0 + nd) * 128 + k0))[k2];
            xs[k2 * 32 + nd] = v;
        }
        // pack W k-pairs: ws[k2][c]
#pragma unroll
        for (int i = 0; i < 16; i++) {
            int idx = tid + i * 256;            // 4096 entries
            int c = idx & 255, k2 = idx >> 8;
            float lo = W1[(long)(k0 + 2 * k2) * 256 + c];
            float hi = W1[(long)(k0 + 2 * k2 + 1) * 256 + c];
            ws[idx] = pack2(lo, hi);
        }
        __syncthreads();
#pragma unroll 2
        for (int k2 = 0; k2 < 16; k2++) {
            ull xv = xs[k2 * 32 + node];
            const ulonglong2* wp = (const ulonglong2*)&ws[k2 * 256 + cbase];
#pragma unroll
            for (int j = 0; j < 16; j++) {
                ulonglong2 wv = wp[j];
                ffma2(acc[2 * j + 0], xv, wv.x);
                ffma2(acc[2 * j + 1], xv, wv.y);
            }
        }
    }

    // epilogue: store h1 (float4s), reduce attention dots deterministically
    float ps = 0.f, pd = 0.f;
#pragma unroll
    for (int j = 0; j < 32; j += 4) {
        float4 o;
        float v, lo, hi;
        unpack2(acc[j + 0], lo, hi); v = lo + hi; o.x = v;
        ps += v * attS[cbase + j + 0]; pd += v * attD[cbase + j + 0];
        unpack2(acc[j + 1], lo, hi); v = lo + hi; o.y = v;
        ps += v * attS[cbase + j + 1]; pd += v * attD[cbase + j + 1];
        unpack2(acc[j + 2], lo, hi); v = lo + hi; o.z = v;
        ps += v * attS[cbase + j + 2]; pd += v * attD[cbase + j + 2];
        unpack2(acc[j + 3], lo, hi); v = lo + hi; o.w = v;
        ps += v * attS[cbase + j + 3]; pd += v * attD[cbase + j + 3];
        if (node < nn)
            *(float4*)(g_h1 + (long)(n0 + node) * 256 + cbase + j) = o;
    }
    s_ps[wi][lane] = ps;
    s_pd[wi][lane] = pd;
    __syncthreads();
    if (tid < 64) {
        int nd = tid & 31, h = tid >> 5;       // head = cg>>2 -> warps h*4..h*4+3
        if (nd < nn) {
            float vs = 0.f, vd = 0.f;
#pragma unroll
            for (int w = 0; w < 4; w++) {
                vs += s_ps[h * 4 + w][nd];
                vd += s_pd[h * 4 + w][nd];
            }
            int gn = n0 + nd;
            g_asrc1[gn * 2 + h] = vs;
            g_adst1[gn * 2 + h] = vd;
        }
    }
}

// ---------------- layer1 edge passes (unchanged from R1) ----------------
__global__ void edgeA1(const int* __restrict__ ei, int E0, int Et) {
    int e = blockIdx.x * blockDim.x + threadIdx.x;
    if (e >= Et) return;
    int s = (e < E0) ? ei[e] : (e - E0);
    int d = (e < E0) ? ei[E0 + e] : (e - E0);
#pragma unroll
    for (int h = 0; h < 2; h++) {
        float v = lrelu(g_asrc1[s * 2 + h] + g_adst1[d * 2 + h]);
        g_e1[e * 2 + h] = v;
        atomicMax(&g_max1[d * 2 + h], fenc(v));
    }
}

__global__ void edgeB1(const int* __restrict__ ei, int E0, int Et) {
    int e = blockIdx.x * blockDim.x + threadIdx.x;
    if (e >= Et) return;
    int d = (e < E0) ? ei[E0 + e] : (e - E0);
#pragma unroll
    for (int h = 0; h < 2; h++) {
        float m = fdec(g_max1[d * 2 + h]);
        float w = __expf(g_e1[e * 2 + h] - m);
        g_e1[e * 2 + h] = w;
        atomicAdd(&g_sum1[d * 2 + h], w);
    }
}

__global__ void scat1(const int* __restrict__ ei, int E0, int Et) {
    int e = (blockIdx.x * blockDim.x + threadIdx.x) >> 5;
    int lane = threadIdx.x & 31;
    if (e >= Et) return;
    int s = (e < E0) ? ei[e] : (e - E0);
    int d = (e < E0) ? ei[E0 + e] : (e - E0);
    float a0 = g_e1[e * 2 + 0] / (g_sum1[d * 2 + 0] + 1e-16f);
    float a1 = g_e1[e * 2 + 1] / (g_sum1[d * 2 + 1] + 1e-16f);
    const float4* hs = (const float4*)(g_h1 + (long)s * 256);
    float* ag = g_agg + (long)d * 256;
    float4 v = hs[lane];
    red4(ag + lane * 4, a0 * v.x, a0 * v.y, a0 * v.z, a0 * v.w);
    v = hs[32 + lane];
    red4(ag + 128 + lane * 4, a1 * v.x, a1 * v.y, a1 * v.z, a1 * v.w);
}

__global__ void fin1(const float* __restrict__ b1, long total) {
    long i = (long)blockIdx.x * blockDim.x + threadIdx.x;
    if (i >= total) return;
    float v = g_agg[i] + b1[i & 255];
    g_agg[i] = v > 0.f ? v : expm1f(v);
}

// ---------------- GEMM2: [hm|hl] = agg @ [Wm|Wl], FFMA2 prepacked ----------------
// 256 threads = 8 warps. M-tile = 64 nodes (2 node-groups). wi = cg*2+ng,
// cg in 0..3: cg 0,1 -> mu cols (0..31 / 32..63); cg 2,3 -> ls cols.
__global__ __launch_bounds__(256, 2) void gemm2(
    const float* __restrict__ Wm, const float* __restrict__ Wl,
    const float* __restrict__ aSm, const float* __restrict__ aDm,
    const float* __restrict__ aSl, const float* __restrict__ aDl, int n)
{
    __shared__ __align__(16) ull xs[16 * 64];    // [k2][node]
    __shared__ __align__(16) ull ws[16 * 128];   // [k2][c]  (c<64 mu, c>=64 ls)
    __shared__ float s_ps[8][32], s_pd[8][32];
    const int tid = threadIdx.x, lane = tid & 31, wi = tid >> 5;
    const int n0 = blockIdx.x * 64;
    const int nn = min(64, n - n0);
    const int ng = wi & 1, cg = wi >> 1;
    const int node = ng * 32 + lane;
    const int cbase = cg * 32;                   // within packed 128-col space

    ull acc[32];
#pragma unroll
    for (int j = 0; j < 32; j++) acc[j] = 0ull;

    for (int k0 = 0; k0 < 256; k0 += 32) {
        __syncthreads();
#pragma unroll
        for (int i = 0; i < 4; i++) {
            int idx = tid + i * 256;            // 1024 entries
            int nd = idx & 63, k2 = idx >> 6;
            ull v = 0ull;
            if (nd < nn)
                v = ((const ull*)(g_agg + (long)(n0 + nd) * 256 + k0))[k2];
            xs[k2 * 64 + nd] = v;
        }
#pragma unroll
        for (int i = 0; i < 8; i++) {
            int idx = tid + i * 256;            // 2048 entries
            int c = idx & 127, k2 = idx >> 7;
            float lo, hi;
            if (c < 64) {
                lo = Wm[(long)(k0 + 2 * k2) * 64 + c];
                hi = Wm[(long)(k0 + 2 * k2 + 1) * 64 + c];
            } else {
                lo = Wl[(long)(k0 + 2 * k2) * 64 + (c - 64)];
                hi = Wl[(long)(k0 + 2 * k2 + 1) * 64 + (c - 64)];
            }
            ws[idx] = pack2(lo, hi);
        }
        __syncthreads();
#pragma unroll 2
        for (int k2 = 0; k2 < 16; k2++) {
            ull xv = xs[k2 * 64 + node];
            const ulonglong2* wp = (const ulonglong2*)&ws[k2 * 128 + cbase];
#pragma unroll
            for (int j = 0; j < 16; j++) {
                ulonglong2 wv = wp[j];
                ffma2(acc[2 * j + 0], xv, wv.x);
                ffma2(acc[2 * j + 1], xv, wv.y);
            }
        }
    }

    // epilogue
    const int isls = cg >> 1;                    // 0 = mu, 1 = ls
    const int cout = (cg & 1) * 32;              // output col base (0 or 32)
    const float* avS = isls ? aSl : aSm;
    const float* avD = isls ? aDl : aDm;
    float* hb = isls ? g_hl : g_hm;

    float ps = 0.f, pd = 0.f;
#pragma unroll
    for (int j = 0; j < 32; j += 4) {
        float4 o;
        float v, lo, hi;
        unpack2(acc[j + 0], lo, hi); v = lo + hi; o.x = v;
        ps += v * avS[cout + j + 0]; pd += v * avD[cout + j + 0];
        unpack2(acc[j + 1], lo, hi); v = lo + hi; o.y = v;
        ps += v * avS[cout + j + 1]; pd += v * avD[cout + j + 1];
        unpack2(acc[j + 2], lo, hi); v = lo + hi; o.z = v;
        ps += v * avS[cout + j + 2]; pd += v * avD[cout + j + 2];
        unpack2(acc[j + 3], lo, hi); v = lo + hi; o.w = v;
        ps += v * avS[cout + j + 3]; pd += v * avD[cout + j + 3];
        if (node < nn)
            *(float4*)(hb + (long)(n0 + node) * 64 + cout + j) = o;
    }
    s_ps[wi][lane] = ps;
    s_pd[wi][lane] = pd;
    __syncthreads();
    if (tid < 128) {
        int nd = tid & 63, q = tid >> 6;         // q: 0 = mu, 1 = ls
        if (nd < nn) {
            int g = nd >> 5, ln = nd & 31;       // node-group, lane
            int gn = n0 + nd;
            if (q == 0) {
                g_asrc_mu[gn] = s_ps[0 + g][ln] + s_ps[2 + g][ln];
                g_adst_mu[gn] = s_pd[0 + g][ln] + s_pd[2 + g][ln];
            } else {
                g_asrc_ls[gn] = s_ps[4 + g][ln] + s_ps[6 + g][ln];
                g_adst_ls[gn] = s_pd[4 + g][ln] + s_pd[6 + g][ln];
            }
        }
    }
}

// ---------------- layer2 edge passes (unchanged from R1) ----------------
__global__ void edgeA2(const int* __restrict__ ei, int E0, int Et) {
    int e = blockIdx.x * blockDim.x + threadIdx.x;
    if (e >= Et) return;
    int s = (e < E0) ? ei[e] : (e - E0);
    int d = (e < E0) ? ei[E0 + e] : (e - E0);
    float vm = lrelu(g_asrc_mu[s] + g_adst_mu[d]);
    g_emu[e] = vm;
    atomicMax(&g_maxmu[d], fenc(vm));
    float vl = lrelu(g_asrc_ls[s] + g_adst_ls[d]);
    g_els[e] = vl;
    atomicMax(&g_maxls[d], fenc(vl));
}

__global__ void edgeB2(const int* __restrict__ ei, int E0, int Et) {
    int e = blockIdx.x * blockDim.x + threadIdx.x;
    if (e >= Et) return;
    int d = (e < E0) ? ei[E0 + e] : (e - E0);
    float wm = __expf(g_emu[e] - fdec(g_maxmu[d]));
    g_emu[e] = wm;
    atomicAdd(&g_summu[d], wm);
    float wl = __expf(g_els[e] - fdec(g_maxls[d]));
    g_els[e] = wl;
    atomicAdd(&g_sumls[d], wl);
}

__global__ void scat2(const int* __restrict__ ei, int E0, int Et, float* out, int n) {
    int e = (blockIdx.x * blockDim.x + threadIdx.x) >> 5;
    int lane = threadIdx.x & 31;
    if (e >= Et) return;
    int s = (e < E0) ? ei[e] : (e - E0);
    int d = (e < E0) ? ei[E0 + e] : (e - E0);
    float am = g_emu[e] / (g_summu[d] + 1e-16f);
    float al = g_els[e] / (g_sumls[d] + 1e-16f);
    const float2* hm = (const float2*)(g_hm + (long)s * 64);
    const float2* hl = (const float2*)(g_hl + (long)s * 64);
    float2 vm = hm[lane];
    red2(out + (long)d * 64 + lane * 2, am * vm.x, am * vm.y);
    float2 vl = hl[lane];
    red2(out + (long)n * 64 + (long)d * 64 + lane * 2, al * vl.x, al * vl.y);
}

__global__ void finbias(float* out, const float* __restrict__ bm,
                        const float* __restrict__ bl, int n) {
    long i = (long)blockIdx.x * blockDim.x + threadIdx.x;
    long half = (long)n * 64;
    if (i >= 2 * half) return;
    int j = (int)(i & 63);
    out[i] += (i >= half) ? bl[j] : bm[j];
}

// ---------------- launch ----------------
extern "C" void kernel_launch(void* const* d_in, const int* in_sizes, int n_in,
                              void* d_out, int out_size) {
    const float* x     = (const float*)d_in[0];
    const int*   ei    = (const int*)d_in[1];
    const float* W1    = (const float*)d_in[2];
    const float* attS1 = (const float*)d_in[3];
    const float* attD1 = (const float*)d_in[4];
    const float* b1    = (const float*)d_in[5];
    const float* Wm    = (const float*)d_in[6];
    const float* aSm   = (const float*)d_in[7];
    const float* aDm   = (const float*)d_in[8];
    const float* bm    = (const float*)d_in[9];
    const float* Wl    = (const float*)d_in[10];
    const float* aSl   = (const float*)d_in[11];
    const float* aDl   = (const float*)d_in[12];
    const float* bl    = (const float*)d_in[13];
    float* out = (float*)d_out;

    int n  = in_sizes[0] / 128;
    int E0 = in_sizes[1] / 2;
    int Et = E0 + n;
    int eb = (Et + 255) / 256;

    long initN = (long)n * 256;
    kinit<<<(int)((initN + 255) / 256), 256>>>(n, out);

    gemm1<<<(n + 31) / 32, 256>>>(x, W1, attS1, attD1, n);

    edgeA1<<<eb, 256>>>(ei, E0, Et);
    edgeB1<<<eb, 256>>>(ei, E0, Et);
    scat1<<<(int)(((long)Et * 32 + 255) / 256), 256>>>(ei, E0, Et);
    fin1<<<(int)(((long)n * 256 + 255) / 256), 256>>>(b1, (long)n * 256);

    gemm2<<<(n + 63) / 64, 256>>>(Wm, Wl, aSm, aDm, aSl, aDl, n);

    edgeA2<<<eb, 256>>>(ei, E0, Et);
    edgeB2<<<eb, 256>>>(ei, E0, Et);
    scat2<<<(int)(((long)Et * 32 + 255) / 256), 256>>>(ei, E0, Et, out, n);
    finbias<<<(int)(((long)2 * n * 64 + 255) / 256), 256>>>(out, bm, bl, n);
}

// round 5
// speedup vs baseline: 1.1839x; 1.1063x over previous
#include <cuda_runtime.h>

#define NMAX 50000
#define EMAX 400000
#define ETOTMAX (EMAX + NMAX)
#define CAP 1024

// ---------------- scratch (device globals; no allocation allowed) ----------------
__device__ __align__(16) float g_h1[NMAX * 256];
__device__ __align__(16) float g_agg[NMAX * 256];
__device__ float g_asrc1[NMAX * 2], g_adst1[NMAX * 2];

__device__ __align__(16) float g_hm[NMAX * 64];
__device__ __align__(16) float g_hl[NMAX * 64];
__device__ float g_asrc_mu[NMAX], g_adst_mu[NMAX];
__device__ float g_asrc_ls[NMAX], g_adst_ls[NMAX];

__device__ int g_cnt[NMAX];
__device__ int g_tmp[NMAX];
__device__ int g_bsum[64], g_boff[64];
__device__ int g_ofs[NMAX + 1];
__device__ int g_cur[NMAX];
__device__ int g_src[ETOTMAX];

// ---------------- helpers ----------------
__device__ __forceinline__ float lrelu(float v) { return v > 0.f ? v : 0.2f * v; }
__device__ __forceinline__ float wredsum(float v) {
#pragma unroll
    for (int o = 16; o; o >>= 1) v += __shfl_xor_sync(0xFFFFFFFFu, v, o);
    return v;
}
__device__ __forceinline__ float wredmax(float v) {
#pragma unroll
    for (int o = 16; o; o >>= 1) v = fmaxf(v, __shfl_xor_sync(0xFFFFFFFFu, v, o));
    return v;
}

// ---------------- CSR build ----------------
__global__ void prep(int n) {
    int i = blockIdx.x * blockDim.x + threadIdx.x;
    if (i < n) g_cnt[i] = 0;
}
__global__ void kcount(const int* __restrict__ ei, int E0, int Et) {
    int e = blockIdx.x * blockDim.x + threadIdx.x;
    if (e >= Et) return;
    int d = (e < E0) ? ei[E0 + e] : (e - E0);
    atomicAdd(&g_cnt[d], 1);
}
// per-block exclusive scan of g_cnt (1024/block); block totals -> g_bsum
__global__ void scanA(int n) {
    __shared__ int wsum[32];
    int tid = threadIdx.x, lane = tid & 31, warp = tid >> 5;
    int i = blockIdx.x * 1024 + tid;
    int v = (i < n) ? g_cnt[i] : 0;
    int x = v;
#pragma unroll
    for (int o = 1; o < 32; o <<= 1) {
        int t = __shfl_up_sync(0xFFFFFFFFu, x, o);
        if (lane >= o) x += t;
    }
    if (lane == 31) wsum[warp] = x;
    __syncthreads();
    if (warp == 0) {
        int s = wsum[lane];
#pragma unroll
        for (int o = 1; o < 32; o <<= 1) {
            int t = __shfl_up_sync(0xFFFFFFFFu, s, o);
            if (lane >= o) s += t;
        }
        wsum[lane] = s;
    }
    __syncthreads();
    int pre = warp ? wsum[warp - 1] : 0;
    int incl = pre + x;
    if (i < n) g_tmp[i] = incl - v;
    if (tid == 1023) g_bsum[blockIdx.x] = incl;
}
// exclusive scan of up to 64 block sums
__global__ void scanB(int nb) {
    __shared__ int w0tot;
    int tid = threadIdx.x, lane = tid & 31, warp = tid >> 5;
    int v = (tid < nb) ? g_bsum[tid] : 0;
    int x = v;
#pragma unroll
    for (int o = 1; o < 32; o <<= 1) {
        int t = __shfl_up_sync(0xFFFFFFFFu, x, o);
        if (lane >= o) x += t;
    }
    if (warp == 0 && lane == 31) w0tot = x;
    __syncthreads();
    int excl = x - v + (warp ? w0tot : 0);
    if (tid < nb) g_boff[tid] = excl;
}
__global__ void scanC(int n, int Et) {
    int i = blockIdx.x * blockDim.x + threadIdx.x;
    if (i < n) {
        int off = g_tmp[i] + g_boff[i >> 10];
        g_ofs[i] = off;
        g_cur[i] = off;
    }
    if (i == 0) g_ofs[n] = Et;
}
__global__ void kfill(const int* __restrict__ ei, int E0, int Et) {
    int e = blockIdx.x * blockDim.x + threadIdx.x;
    if (e >= Et) return;
    int s = (e < E0) ? ei[e] : (e - E0);
    int d = (e < E0) ? ei[E0 + e] : (e - E0);
    int pos = atomicAdd(&g_cur[d], 1);
    g_src[pos] = s;
}

// ---------------- GEMM1 (R1 proven version): h1 = x @ W1 + attention dots ------
// 256 threads, 8 nodes/block. thread j computes h1[n, j] for 8 nodes.
__global__ void gemm1(const float* __restrict__ x, const float* __restrict__ W1,
                      const float* __restrict__ attS, const float* __restrict__ attD,
                      int n) {
    __shared__ float xs[8 * 128];
    __shared__ float redS[8][8];
    __shared__ float redD[8][8];
    const int tid = threadIdx.x;
    const int n0 = blockIdx.x * 8;
    const int nn = min(8, n - n0);

    for (int idx = tid; idx < nn * 128; idx += 256) xs[idx] = x[(long)n0 * 128 + idx];
    __syncthreads();

    const float av_s = attS[tid];
    const float av_d = attD[tid];

    float acc[8];
#pragma unroll
    for (int i = 0; i < 8; i++) acc[i] = 0.f;

#pragma unroll 4
    for (int k = 0; k < 128; k += 4) {
        float w0 = W1[(k + 0) * 256 + tid];
        float w1 = W1[(k + 1) * 256 + tid];
        float w2 = W1[(k + 2) * 256 + tid];
        float w3 = W1[(k + 3) * 256 + tid];
#pragma unroll
        for (int i = 0; i < 8; i++) {
            float4 xv = *(const float4*)&xs[i * 128 + k];
            acc[i] += xv.x * w0 + xv.y * w1 + xv.z * w2 + xv.w * w3;
        }
    }

    const int warp = tid >> 5, lane = tid & 31;
    for (int i = 0; i < nn; i++) {
        g_h1[(long)(n0 + i) * 256 + tid] = acc[i];
        float ss = acc[i] * av_s, sd = acc[i] * av_d;
#pragma unroll
        for (int o = 16; o; o >>= 1) {
            ss += __shfl_down_sync(0xFFFFFFFFu, ss, o);
            sd += __shfl_down_sync(0xFFFFFFFFu, sd, o);
        }
        if (lane == 0) { redS[warp][i] = ss; redD[warp][i] = sd; }
    }
    __syncthreads();
    if (tid < 32) {
        int i = tid & 7, h = (tid >> 3) & 1, isD = tid >> 4;
        if (i < nn) {
            float v = 0.f;
#pragma unroll
            for (int w = 0; w < 4; w++) v += isD ? redD[h * 4 + w][i] : redS[h * 4 + w][i];
            if (isD) g_adst1[(n0 + i) * 2 + h] = v;
            else     g_asrc1[(n0 + i) * 2 + h] = v;
        }
    }
}

// ---------------- gather1: fused softmax + aggregate + bias + ELU ----------------
__global__ __launch_bounds__(256) void gather1(const float* __restrict__ b1) {
    __shared__ int   s_src[CAP];
    __shared__ float s_w0[CAP], s_w1[CAP];
    __shared__ float par[6];
    const int d = blockIdx.x;
    const int tid = threadIdx.x, lane = tid & 31;
    const int beg = g_ofs[d];
    const int deg = g_ofs[d + 1] - beg;

    if (tid < 32) {
        float ad0 = g_adst1[2 * d], ad1 = g_adst1[2 * d + 1];
        float m0 = -1e30f, m1 = -1e30f;
        for (int i = lane; i < deg; i += 32) {
            int s = g_src[beg + i];
            float2 a = ((const float2*)g_asrc1)[s];
            float v0 = lrelu(a.x + ad0), v1 = lrelu(a.y + ad1);
            if (i < CAP) { s_src[i] = s; s_w0[i] = v0; s_w1[i] = v1; }
            m0 = fmaxf(m0, v0); m1 = fmaxf(m1, v1);
        }
        m0 = wredmax(m0); m1 = wredmax(m1);
        float t0 = 0.f, t1 = 0.f;
        for (int i = lane; i < deg; i += 32) {
            float v0, v1;
            if (i < CAP) { v0 = s_w0[i]; v1 = s_w1[i]; }
            else {
                int s = g_src[beg + i];
                float2 a = ((const float2*)g_asrc1)[s];
                v0 = lrelu(a.x + ad0); v1 = lrelu(a.y + ad1);
            }
            float w0 = __expf(v0 - m0), w1 = __expf(v1 - m1);
            if (i < CAP) { s_w0[i] = w0; s_w1[i] = w1; }
            t0 += w0; t1 += w1;
        }
        t0 = wredsum(t0); t1 = wredsum(t1);
        if (lane == 0) {
            par[0] = m0; par[1] = m1;
            par[2] = 1.f / (t0 + 1e-16f); par[3] = 1.f / (t1 + 1e-16f);
            par[4] = ad0; par[5] = ad1;
        }
    }
    __syncthreads();

    const int h = tid >> 7;
    const float* sw = h ? s_w1 : s_w0;
    const float inv = par[2 + h];
    const float* hbase = g_h1 + tid;
    float a0 = 0.f, a1 = 0.f, a2 = 0.f, a3 = 0.f;
    const int dc = min(deg, CAP);
    int i = 0;
    for (; i + 4 <= dc; i += 4) {
        int s0 = s_src[i], s1 = s_src[i + 1], s2 = s_src[i + 2], s3 = s_src[i + 3];
        float w0 = sw[i], w1 = sw[i + 1], w2 = sw[i + 2], w3 = sw[i + 3];
        float v0 = hbase[(long)s0 * 256];
        float v1 = hbase[(long)s1 * 256];
        float v2 = hbase[(long)s2 * 256];
        float v3 = hbase[(long)s3 * 256];
        a0 += w0 * v0; a1 += w1 * v1; a2 += w2 * v2; a3 += w3 * v3;
    }
    for (; i < dc; i++) a0 += sw[i] * hbase[(long)s_src[i] * 256];
    if (deg > CAP) {
        float m = par[h], adh = par[4 + h];
        for (int j = CAP; j < deg; j++) {
            int s = g_src[beg + j];
            float v = lrelu(g_asrc1[2 * s + h] + adh);
            a0 += __expf(v - m) * hbase[(long)s * 256];
        }
    }
    float acc = (a0 + a1) + (a2 + a3);
    float val = acc * inv + b1[tid];
    g_agg[(long)d * 256 + tid] = val > 0.f ? val : expm1f(val);
}

// ---------------- GEMM2 (R1 proven version): [hm|hl] = agg @ [Wm|Wl] ------------
// 128 threads: 0..63 mu channel j, 64..127 ls channel j. 8 nodes/block.
__global__ void gemm2(const float* __restrict__ Wm, const float* __restrict__ Wl,
                      const float* __restrict__ aSm, const float* __restrict__ aDm,
                      const float* __restrict__ aSl, const float* __restrict__ aDl,
                      int n) {
    __shared__ float hs[8 * 256];
    __shared__ float redS[4][8];
    __shared__ float redD[4][8];
    const int tid = threadIdx.x;
    const int n0 = blockIdx.x * 8;
    const int nn = min(8, n - n0);
    const int half = tid >> 6;
    const int j = tid & 63;

    for (int idx = tid; idx < nn * 256; idx += 128) hs[idx] = g_agg[(long)n0 * 256 + idx];
    __syncthreads();

    const float* W = half ? Wl : Wm;
    const float av_s = half ? aSl[j] : aSm[j];
    const float av_d = half ? aDl[j] : aDm[j];

    float acc[8];
#pragma unroll
    for (int i = 0; i < 8; i++) acc[i] = 0.f;

#pragma unroll 4
    for (int k = 0; k < 256; k += 4) {
        float w0 = W[(k + 0) * 64 + j];
        float w1 = W[(k + 1) * 64 + j];
        float w2 = W[(k + 2) * 64 + j];
        float w3 = W[(k + 3) * 64 + j];
#pragma unroll
        for (int i = 0; i < 8; i++) {
            float4 xv = *(const float4*)&hs[i * 256 + k];
            acc[i] += xv.x * w0 + xv.y * w1 + xv.z * w2 + xv.w * w3;
        }
    }

    const int warp = tid >> 5, lane = tid & 31;
    float* dstbuf = half ? g_hl : g_hm;
    for (int i = 0; i < nn; i++) {
        dstbuf[(long)(n0 + i) * 64 + j] = acc[i];
        float ss = acc[i] * av_s, sd = acc[i] * av_d;
#pragma unroll
        for (int o = 16; o; o >>= 1) {
            ss += __shfl_down_sync(0xFFFFFFFFu, ss, o);
            sd += __shfl_down_sync(0xFFFFFFFFu, sd, o);
        }
        if (lane == 0) { redS[warp][i] = ss; redD[warp][i] = sd; }
    }
    __syncthreads();
    if (tid < 32) {
        int i = tid & 7, code = tid >> 3;
        if (i < nn) {
            int node = n0 + i;
            if (code == 0) g_asrc_mu[node] = redS[0][i] + redS[1][i];
            if (code == 1) g_adst_mu[node] = redD[0][i] + redD[1][i];
            if (code == 2) g_asrc_ls[node] = redS[2][i] + redS[3][i];
            if (code == 3) g_adst_ls[node] = redD[2][i] + redD[3][i];
        }
    }
}

// ---------------- gather2: fused softmax + aggregate + bias (mu & logstd) -------
__global__ __launch_bounds__(128) void gather2(
    float* __restrict__ out, const float* __restrict__ bm,
    const float* __restrict__ bl, int n)
{
    __shared__ int   s_src[CAP];
    __shared__ float s_wm[CAP], s_wl[CAP];
    __shared__ float par[6];
    const int d = blockIdx.x;
    const int tid = threadIdx.x, lane = tid & 31;
    const int beg = g_ofs[d];
    const int deg = g_ofs[d + 1] - beg;

    if (tid < 32) {
        float adm = g_adst_mu[d], adl = g_adst_ls[d];
        float mm = -1e30f, ml = -1e30f;
        for (int i = lane; i < deg; i += 32) {
            int s = g_src[beg + i];
            float vm = lrelu(g_asrc_mu[s] + adm);
            float vl = lrelu(g_asrc_ls[s] + adl);
            if (i < CAP) { s_src[i] = s; s_wm[i] = vm; s_wl[i] = vl; }
            mm = fmaxf(mm, vm); ml = fmaxf(ml, vl);
        }
        mm = wredmax(mm); ml = wredmax(ml);
        float tm = 0.f, tl = 0.f;
        for (int i = lane; i < deg; i += 32) {
            float vm, vl;
            if (i < CAP) { vm = s_wm[i]; vl = s_wl[i]; }
            else {
                int s = g_src[beg + i];
                vm = lrelu(g_asrc_mu[s] + adm);
                vl = lrelu(g_asrc_ls[s] + adl);
            }
            float wm = __expf(vm - mm), wl = __expf(vl - ml);
            if (i < CAP) { s_wm[i] = wm; s_wl[i] = wl; }
            tm += wm; tl += wl;
        }
        tm = wredsum(tm); tl = wredsum(tl);
        if (lane == 0) {
            par[0] = mm; par[1] = ml;
            par[2] = 1.f / (tm + 1e-16f); par[3] = 1.f / (tl + 1e-16f);
            par[4] = adm; par[5] = adl;
        }
    }
    __syncthreads();

    const int grp = tid >> 6;         // 0 = mu, 1 = ls
    const int c = tid & 63;
    const float* hb = grp ? g_hl : g_hm;
    const float* sw = grp ? s_wl : s_wm;
    const float inv = par[2 + grp];
    const float* hbase = hb + c;
    float a0 = 0.f, a1 = 0.f, a2 = 0.f, a3 = 0.f;
    const int dc = min(deg, CAP);
    int i = 0;
    for (; i + 4 <= dc; i += 4) {
        int s0 = s_src[i], s1 = s_src[i + 1], s2 = s_src[i + 2], s3 = s_src[i + 3];
        float w0 = sw[i], w1 = sw[i + 1], w2 = sw[i + 2], w3 = sw[i + 3];
        float v0 = hbase[(long)s0 * 64];
        float v1 = hbase[(long)s1 * 64];
        float v2 = hbase[(long)s2 * 64];
        float v3 = hbase[(long)s3 * 64];
        a0 += w0 * v0; a1 += w1 * v1; a2 += w2 * v2; a3 += w3 * v3;
    }
    for (; i < dc; i++) a0 += sw[i] * hbase[(long)s_src[i] * 64];
    if (deg > CAP) {
        float m = par[grp], adh = par[4 + grp];
        const float* asc = grp ? g_asrc_ls : g_asrc_mu;
        for (int j2 = CAP; j2 < deg; j2++) {
            int s = g_src[beg + j2];
            float v = lrelu(asc[s] + adh);
            a0 += __expf(v - m) * hbase[(long)s * 64];
        }
    }
    float acc = (a0 + a1) + (a2 + a3);
    float bias = grp ? bl[c] : bm[c];
    long off = grp ? ((long)(n + d) * 64 + c) : ((long)d * 64 + c);
    out[off] = acc * inv + bias;
}

// ---------------- launch ----------------
extern "C" void kernel_launch(void* const* d_in, const int* in_sizes, int n_in,
                              void* d_out, int out_size) {
    const float* x     = (const float*)d_in[0];
    const int*   ei    = (const int*)d_in[1];
    const float* W1    = (const float*)d_in[2];
    const float* attS1 = (const float*)d_in[3];
    const float* attD1 = (const float*)d_in[4];
    const float* b1    = (const float*)d_in[5];
    const float* Wm    = (const float*)d_in[6];
    const float* aSm   = (const float*)d_in[7];
    const float* aDm   = (const float*)d_in[8];
    const float* bm    = (const float*)d_in[9];
    const float* Wl    = (const float*)d_in[10];
    const float* aSl   = (const float*)d_in[11];
    const float* aDl   = (const float*)d_in[12];
    const float* bl    = (const float*)d_in[13];
    float* out = (float*)d_out;

    int n  = in_sizes[0] / 128;
    int E0 = in_sizes[1] / 2;
    int Et = E0 + n;
    int eb = (Et + 255) / 256;
    int nb = (n + 1023) / 1024;

    prep<<<nb, 1024>>>(n);
    kcount<<<eb, 256>>>(ei, E0, Et);
    scanA<<<nb, 1024>>>(n);
    scanB<<<1, 64>>>(nb);
    scanC<<<nb, 1024>>>(n, Et);
    kfill<<<eb, 256>>>(ei, E0, Et);

    gemm1<<<(n + 7) / 8, 256>>>(x, W1, attS1, attD1, n);
    gather1<<<n, 256>>>(b1);
    gemm2<<<(n + 7) / 8, 128>>>(Wm, Wl, aSm, aDm, aSl, aDl, n);
    gather2<<<n, 128>>>(out, bm, bl, n);
}